// round 1
// baseline (speedup 1.0000x reference)
#include <cuda_runtime.h>
#include <cuda_bf16.h>

// Problem constants (fixed shapes for this problem)
#define N_ROWS   131072      // B*H*W = 32*64*64
#define DDIM     64
#define KCB      1024
#define DECAY    0.99f
#define ONEMD    0.01f       // 1 - DECAY
#define EPS      1e-5f

#define KT       128         // codebook columns per smem tile
#define PAD      68          // smem row pitch (floats), multiple of 4, avoids 32-way conflicts

// Output layout (flattened tuple: quantized_st, loss, new_codebook, new_ecs, new_eis)
#define OFF_Q    0
#define OFF_LOSS (N_ROWS*DDIM)                 // 8388608
#define OFF_NCB  (OFF_LOSS + 1)                // 8388609
#define OFF_ECS  (OFF_NCB + DDIM*KCB)          // 8454145
#define OFF_EIS  (OFF_ECS + KCB)               // 8455169

// Scratch (device globals; no allocations allowed)
__device__ int   g_idx[N_ROWS];
__device__ float g_counts[KCB];
__device__ float g_isum[KCB * DDIM];   // [k][d] layout
__device__ float g_l2cb[KCB];
__device__ float g_ncbT[KCB * DDIM];   // new codebook transposed [k][d]
__device__ float g_loss[1];

// ---------------------------------------------------------------------------
// Kernel 0: zero scratch + precompute ||c_k||^2
// ---------------------------------------------------------------------------
__global__ void k_init(const float* __restrict__ cb) {
    int i = blockIdx.x * blockDim.x + threadIdx.x;
    if (i < KCB * DDIM) g_isum[i] = 0.0f;
    if (i < KCB) {
        g_counts[i] = 0.0f;
        float s = 0.0f;
        #pragma unroll
        for (int d = 0; d < DDIM; ++d) {
            float c = cb[d * KCB + i];   // coalesced across i
            s = fmaf(c, c, s);
        }
        g_l2cb[i] = s;
    }
    if (i == 0) g_loss[0] = 0.0f;
}

// ---------------------------------------------------------------------------
// Kernel A: per-row argmin over K codewords + fused scatter-add statistics
// Persistent grid; each chunk = 256 rows handled by one block pass.
// ---------------------------------------------------------------------------
__global__ __launch_bounds__(256, 2) void k_argmin_scatter(
        const float* __restrict__ X, const float* __restrict__ CB)
{
    __shared__ float s_cb[KT * PAD];
    __shared__ float s_l2[KT];
    const int tid = threadIdx.x;

    for (int chunk = blockIdx.x; chunk < N_ROWS / 256; chunk += gridDim.x) {
        const int row = chunk * 256 + tid;   // N_ROWS is an exact multiple of 256

        // Load this thread's row into registers + compute ||x||^2
        float4 xv[16];
        const float4* xr = reinterpret_cast<const float4*>(X + (size_t)row * DDIM);
        float l0 = 0.f, l1 = 0.f, l2 = 0.f, l3 = 0.f;
        #pragma unroll
        for (int j = 0; j < 16; ++j) {
            xv[j] = xr[j];
            l0 = fmaf(xv[j].x, xv[j].x, l0);
            l1 = fmaf(xv[j].y, xv[j].y, l1);
            l2 = fmaf(xv[j].z, xv[j].z, l2);
            l3 = fmaf(xv[j].w, xv[j].w, l3);
        }
        const float l2x = (l0 + l1) + (l2 + l3);

        float best = __int_as_float(0x7f800000);  // +inf
        int bidx = 0;

        for (int t = 0; t < KCB / KT; ++t) {
            __syncthreads();
            // Cooperative tile load: k-consecutive across lanes -> coalesced GMEM
            #pragma unroll
            for (int i = tid; i < KT * DDIM; i += 256) {
                int k = i & (KT - 1);
                int d = i >> 7;   // KT = 128
                s_cb[k * PAD + d] = CB[d * KCB + t * KT + k];
            }
            if (tid < KT) s_l2[tid] = g_l2cb[t * KT + tid];
            __syncthreads();

            #pragma unroll 2
            for (int k = 0; k < KT; ++k) {
                const float4* c4 = reinterpret_cast<const float4*>(&s_cb[k * PAD]);
                float a0 = 0.f, a1 = 0.f, a2 = 0.f, a3 = 0.f;
                #pragma unroll
                for (int j = 0; j < 16; ++j) {
                    float4 c = c4[j];   // warp-broadcast LDS.128
                    a0 = fmaf(xv[j].x, c.x, a0);
                    a1 = fmaf(xv[j].y, c.y, a1);
                    a2 = fmaf(xv[j].z, c.z, a2);
                    a3 = fmaf(xv[j].w, c.w, a3);
                }
                float dot  = (a0 + a1) + (a2 + a3);
                float dist = (l2x - 2.0f * dot) + s_l2[k];
                if (dist < best) { best = dist; bidx = t * KT + k; }
            }
        }

        g_idx[row] = bidx;
        atomicAdd(&g_counts[bidx], 1.0f);
        float* dst = &g_isum[bidx * DDIM];
        #pragma unroll
        for (int j = 0; j < 16; ++j) {
            atomicAdd(dst + 4 * j + 0, xv[j].x);
            atomicAdd(dst + 4 * j + 1, xv[j].y);
            atomicAdd(dst + 4 * j + 2, xv[j].z);
            atomicAdd(dst + 4 * j + 3, xv[j].w);
        }
    }
}

// ---------------------------------------------------------------------------
// Kernel B: EMA update, normalization, new codebook (+ transposed copy)
// Single block of 1024 threads (one per k).
// ---------------------------------------------------------------------------
__global__ __launch_bounds__(1024) void k_ema(
        const float* __restrict__ ema_cs,
        const float* __restrict__ ema_eis,
        float* __restrict__ out)
{
    __shared__ float red[1024];
    const int k = threadIdx.x;

    float ne = DECAY * ema_cs[k] + ONEMD * g_counts[k];
    out[OFF_ECS + k] = ne;

    red[k] = ne;
    __syncthreads();
    for (int s = 512; s > 0; s >>= 1) {
        if (k < s) red[k] += red[k + s];
        __syncthreads();
    }
    const float n = red[0];

    const float norm = (ne + EPS) / (n + (float)KCB * EPS);
    const float cs   = norm * n;
    const float inv_cs = 1.0f / cs;

    #pragma unroll
    for (int d = 0; d < DDIM; ++d) {
        float eis = DECAY * ema_eis[d * KCB + k] + ONEMD * g_isum[k * DDIM + d];
        out[OFF_EIS + d * KCB + k] = eis;
        float nc = eis * inv_cs;
        out[OFF_NCB + d * KCB + k] = nc;
        g_ncbT[k * DDIM + d] = nc;
    }
}

// ---------------------------------------------------------------------------
// Kernel C: gather quantized output (straight-through) + loss accumulation
// ---------------------------------------------------------------------------
__global__ __launch_bounds__(256) void k_gather_loss(
        const float* __restrict__ X, float* __restrict__ out)
{
    float acc = 0.0f;
    const int total = N_ROWS * DDIM;
    for (int e = blockIdx.x * blockDim.x + threadIdx.x; e < total;
         e += gridDim.x * blockDim.x) {
        int n = e >> 6;
        int d = e & 63;
        float q  = g_ncbT[(g_idx[n] << 6) | d];   // coalesced (idx shared per half-row)
        float xv = X[e];
        float t  = q - xv;
        out[OFF_Q + e] = xv + t;   // mirrors reference's x + (q - x) rounding
        acc = fmaf(t, t, acc);
    }
    // warp reduce
    #pragma unroll
    for (int o = 16; o > 0; o >>= 1)
        acc += __shfl_down_sync(0xffffffffu, acc, o);
    __shared__ float warpsum[8];
    int lane = threadIdx.x & 31, wid = threadIdx.x >> 5;
    if (lane == 0) warpsum[wid] = acc;
    __syncthreads();
    if (wid == 0) {
        float v = (lane < 8) ? warpsum[lane] : 0.0f;
        #pragma unroll
        for (int o = 4; o > 0; o >>= 1)
            v += __shfl_down_sync(0xffffffffu, v, o);
        if (lane == 0) atomicAdd(g_loss, v);
    }
}

// ---------------------------------------------------------------------------
// Kernel D: finalize the mean loss
// ---------------------------------------------------------------------------
__global__ void k_loss_finalize(float* __restrict__ out) {
    out[OFF_LOSS] = g_loss[0] * (1.0f / (float)(N_ROWS * DDIM));
}

// ---------------------------------------------------------------------------
extern "C" void kernel_launch(void* const* d_in, const int* in_sizes, int n_in,
                              void* d_out, int out_size) {
    const float* X       = (const float*)d_in[0];  // inputs [B,H,W,D]
    const float* CB      = (const float*)d_in[1];  // codebook [D,K]
    const float* EMA_CS  = (const float*)d_in[2];  // ema_cluster_size [K]
    const float* EMA_EIS = (const float*)d_in[3];  // ema_input_sum [D,K]
    float* out = (float*)d_out;

    k_init<<<256, 256>>>(CB);
    k_argmin_scatter<<<296, 256>>>(X, CB);
    k_ema<<<1, 1024>>>(EMA_CS, EMA_EIS, out);
    k_gather_loss<<<2048, 256>>>(X, out);
    k_loss_finalize<<<1, 1>>>(out);
}

// round 2
// speedup vs baseline: 2.9008x; 2.9008x over previous
#include <cuda_runtime.h>
#include <cuda_bf16.h>
#include <cstdint>

// Problem constants
#define N_ROWS   131072      // B*H*W = 32*64*64
#define DDIM     64
#define KCB      1024
#define DECAY    0.99f
#define ONEMD    0.01f
#define EPS      1e-5f

#define KT       64          // codebook columns per smem tile
#define NTILES   (KCB / KT)  // 16
#define TILE_FLOATS (2 * 8 * KT * 8)   // splits * ksteps * n * 8 = 8192 floats = 32KB

// Output layout (flattened tuple)
#define OFF_Q    0
#define OFF_LOSS (N_ROWS*DDIM)
#define OFF_NCB  (OFF_LOSS + 1)
#define OFF_ECS  (OFF_NCB + DDIM*KCB)
#define OFF_EIS  (OFF_ECS + KCB)

// Scratch
__device__ int   g_idx[N_ROWS];
__device__ float g_counts[KCB];
__device__ float g_isum[KCB * DDIM];        // [k][d]
__device__ float g_l2cb[KCB];
__device__ float g_ncbT[KCB * DDIM];        // [k][d]
__device__ float g_loss[1];
__device__ float g_cbsplit[2 * KCB * DDIM]; // tile-ordered tf32 hi/lo image (512KB)

// ---------------------------------------------------------------------------
__device__ __forceinline__ void split_tf32(float x, uint32_t& h, uint32_t& l) {
    uint32_t hb;
    asm("cvt.rna.tf32.f32 %0, %1;" : "=r"(hb) : "f"(x));
    float lf = x - __uint_as_float(hb);
    uint32_t lb;
    asm("cvt.rna.tf32.f32 %0, %1;" : "=r"(lb) : "f"(lf));
    h = hb; l = lb;
}

__device__ __forceinline__ void mma8(float c[4], const uint32_t a[4],
                                     uint32_t b0, uint32_t b1) {
    asm volatile(
        "mma.sync.aligned.m16n8k8.row.col.f32.tf32.tf32.f32 "
        "{%0,%1,%2,%3},{%4,%5,%6,%7},{%8,%9},{%0,%1,%2,%3};"
        : "+f"(c[0]), "+f"(c[1]), "+f"(c[2]), "+f"(c[3])
        : "r"(a[0]), "r"(a[1]), "r"(a[2]), "r"(a[3]), "r"(b0), "r"(b1));
}

__device__ __forceinline__ void cp_async16(uint32_t smem_dst, const void* gsrc) {
    asm volatile("cp.async.cg.shared.global [%0], [%1], 16;"
                 :: "r"(smem_dst), "l"(gsrc));
}
__device__ __forceinline__ void cp_commit() {
    asm volatile("cp.async.commit_group;");
}

// ---------------------------------------------------------------------------
// Kernel 0: zero scratch, ||c_k||^2, and build tile-ordered tf32 split image.
// Grid 256 x 256 = 65536 threads, one per (n,d).
// ---------------------------------------------------------------------------
__global__ void k_init(const float* __restrict__ cb) {
    int i = blockIdx.x * blockDim.x + threadIdx.x;   // 0..65535
    int n = i & (KCB - 1);
    int d = i >> 10;

    g_isum[i] = 0.0f;

    // split image: tile tt holds cols [tt*KT, tt*KT+KT)
    float x = cb[d * KCB + n];          // coalesced in n
    uint32_t h, l;
    split_tf32(x, h, l);
    int tt = n / KT;
    int nl = n % KT;
    int ks = d >> 3;
    int dd = d & 7;
    int t  = dd & 3;
    int hh = dd >> 2;                   // 0 -> k=t, 1 -> k=t+4
    int base = tt * TILE_FLOATS;
    g_cbsplit[base + ((0 * 8 + ks) * KT + nl) * 8 + t * 2 + hh] = __uint_as_float(h);
    g_cbsplit[base + ((1 * 8 + ks) * KT + nl) * 8 + t * 2 + hh] = __uint_as_float(l);

    if (i < KCB) {
        g_counts[i] = 0.0f;
        float s = 0.0f;
        #pragma unroll
        for (int dj = 0; dj < DDIM; ++dj) {
            float c = cb[dj * KCB + i];
            s = fmaf(c, c, s);
        }
        g_l2cb[i] = s;
    }
    if (i == 0) g_loss[0] = 0.0f;
}

// ---------------------------------------------------------------------------
// Kernel A: tensor-core argmin (tf32 x3 split) + fused scatter statistics.
// 256 threads/block, 8 warps, 16 rows/warp -> 128 rows/block, grid = 1024.
// dynamic smem: s_l2[1024] then 2 x TILE_FLOATS buffers.
// ---------------------------------------------------------------------------
extern __shared__ float s_dyn[];

__global__ __launch_bounds__(256, 2) void k_argmin_scatter(
        const float* __restrict__ X)
{
    float* s_l2 = s_dyn;                       // 1024 floats
    float* s_b  = s_dyn + KCB;                 // 2 * TILE_FLOATS

    const int tid  = threadIdx.x;
    const int wid  = tid >> 5;
    const int lane = tid & 31;
    const int g    = lane >> 2;                // row group 0..7
    const int t    = lane & 3;

    const int base_row = blockIdx.x * 128 + wid * 16;
    const int r0 = base_row + g;
    const int r1 = r0 + 8;

    // stage l2cb (once)
    for (int i = tid; i < KCB; i += 256) s_l2[i] = g_l2cb[i];

    // Load A fragments for both rows across full D, split into tf32 hi/lo.
    uint32_t Ah[8][4], Al[8][4];
    #pragma unroll
    for (int ks = 0; ks < 8; ++ks) {
        float a0 = X[(size_t)r0 * DDIM + ks * 8 + t];
        float a1 = X[(size_t)r1 * DDIM + ks * 8 + t];
        float a2 = X[(size_t)r0 * DDIM + ks * 8 + t + 4];
        float a3 = X[(size_t)r1 * DDIM + ks * 8 + t + 4];
        split_tf32(a0, Ah[ks][0], Al[ks][0]);
        split_tf32(a1, Ah[ks][1], Al[ks][1]);
        split_tf32(a2, Ah[ks][2], Al[ks][2]);
        split_tf32(a3, Ah[ks][3], Al[ks][3]);
    }

    // cp.async staging helper (inline): tile tt -> buffer b
    const uint32_t sb_base = (uint32_t)__cvta_generic_to_shared(s_b);
    auto stage = [&](int tt, int b) {
        const float4* src = reinterpret_cast<const float4*>(g_cbsplit + tt * TILE_FLOATS);
        uint32_t dst = sb_base + (uint32_t)(b * TILE_FLOATS * 4);
        #pragma unroll
        for (int j = 0; j < TILE_FLOATS / 4 / 256; ++j) {   // 8 per thread
            int e = tid + j * 256;
            cp_async16(dst + e * 16, src + e);
        }
        cp_commit();
    };

    stage(0, 0);
    stage(1, 1);

    float bv0 = __int_as_float(0x7f800000), bv1 = bv0;
    int   bi0 = 0, bi1 = 0;

    for (int tt = 0; tt < NTILES; ++tt) {
        if (tt == NTILES - 1) { asm volatile("cp.async.wait_group 0;"); }
        else                  { asm volatile("cp.async.wait_group 1;"); }
        __syncthreads();

        const float* sb = s_b + (tt & 1) * TILE_FLOATS;

        #pragma unroll
        for (int sp = 0; sp < 4; ++sp) {
            const int nl0 = (2 * sp + 0) * 8 + g;
            const int nl1 = (2 * sp + 1) * 8 + g;
            float c0[4] = {0.f, 0.f, 0.f, 0.f};
            float c1[4] = {0.f, 0.f, 0.f, 0.f};

            #pragma unroll
            for (int ks = 0; ks < 8; ++ks) {
                float2 bh0 = *reinterpret_cast<const float2*>(
                    &sb[((0 * 8 + ks) * KT + nl0) * 8 + 2 * t]);
                float2 bl0 = *reinterpret_cast<const float2*>(
                    &sb[((1 * 8 + ks) * KT + nl0) * 8 + 2 * t]);
                float2 bh1 = *reinterpret_cast<const float2*>(
                    &sb[((0 * 8 + ks) * KT + nl1) * 8 + 2 * t]);
                float2 bl1 = *reinterpret_cast<const float2*>(
                    &sb[((1 * 8 + ks) * KT + nl1) * 8 + 2 * t]);

                uint32_t bh0x = __float_as_uint(bh0.x), bh0y = __float_as_uint(bh0.y);
                uint32_t bl0x = __float_as_uint(bl0.x), bl0y = __float_as_uint(bl0.y);
                uint32_t bh1x = __float_as_uint(bh1.x), bh1y = __float_as_uint(bh1.y);
                uint32_t bl1x = __float_as_uint(bl1.x), bl1y = __float_as_uint(bl1.y);

                mma8(c0, Ah[ks], bh0x, bh0y);
                mma8(c0, Al[ks], bh0x, bh0y);
                mma8(c0, Ah[ks], bl0x, bl0y);
                mma8(c1, Ah[ks], bh1x, bh1y);
                mma8(c1, Al[ks], bh1x, bh1y);
                mma8(c1, Ah[ks], bl1x, bl1y);
            }

            // epilogue: score = l2cb - 2*dot ; argmin update (cols ascending)
            {
                const int col0 = tt * KT + (2 * sp + 0) * 8 + 2 * t;
                float2 l2p = *reinterpret_cast<const float2*>(&s_l2[col0]);
                float s0 = fmaf(-2.f, c0[0], l2p.x);
                float s1 = fmaf(-2.f, c0[1], l2p.y);
                float s2 = fmaf(-2.f, c0[2], l2p.x);
                float s3 = fmaf(-2.f, c0[3], l2p.y);
                if (s0 < bv0) { bv0 = s0; bi0 = col0; }
                if (s1 < bv0) { bv0 = s1; bi0 = col0 + 1; }
                if (s2 < bv1) { bv1 = s2; bi1 = col0; }
                if (s3 < bv1) { bv1 = s3; bi1 = col0 + 1; }
            }
            {
                const int col1 = tt * KT + (2 * sp + 1) * 8 + 2 * t;
                float2 l2p = *reinterpret_cast<const float2*>(&s_l2[col1]);
                float s0 = fmaf(-2.f, c1[0], l2p.x);
                float s1 = fmaf(-2.f, c1[1], l2p.y);
                float s2 = fmaf(-2.f, c1[2], l2p.x);
                float s3 = fmaf(-2.f, c1[3], l2p.y);
                if (s0 < bv0) { bv0 = s0; bi0 = col1; }
                if (s1 < bv0) { bv0 = s1; bi0 = col1 + 1; }
                if (s2 < bv1) { bv1 = s2; bi1 = col1; }
                if (s3 < bv1) { bv1 = s3; bi1 = col1 + 1; }
            }
        }

        __syncthreads();
        if (tt + 2 < NTILES) stage(tt + 2, tt & 1);
    }

    // Reduce argmin across the 4 threads of each row group (xor -> all lanes)
    #pragma unroll
    for (int off = 1; off < 4; off <<= 1) {
        float ov0 = __shfl_xor_sync(0xffffffffu, bv0, off);
        int   oi0 = __shfl_xor_sync(0xffffffffu, bi0, off);
        if (ov0 < bv0 || (ov0 == bv0 && oi0 < bi0)) { bv0 = ov0; bi0 = oi0; }
        float ov1 = __shfl_xor_sync(0xffffffffu, bv1, off);
        int   oi1 = __shfl_xor_sync(0xffffffffu, bi1, off);
        if (ov1 < bv1 || (ov1 == bv1 && oi1 < bi1)) { bv1 = ov1; bi1 = oi1; }
    }

    if (t == 0) {
        g_idx[r0] = bi0;
        atomicAdd(&g_counts[bi0], 1.0f);
        g_idx[r1] = bi1;
        atomicAdd(&g_counts[bi1], 1.0f);
    }

    // Scatter input sums: 16 rows x 64 dims per warp
    #pragma unroll
    for (int r = 0; r < 16; ++r) {
        int src_lane = (r & 7) * 4;
        int idx = (r < 8) ? __shfl_sync(0xffffffffu, bi0, src_lane)
                          : __shfl_sync(0xffffffffu, bi1, src_lane);
        int row = base_row + r;
        float v0 = X[(size_t)row * DDIM + lane];
        float v1 = X[(size_t)row * DDIM + lane + 32];
        atomicAdd(&g_isum[idx * DDIM + lane], v0);
        atomicAdd(&g_isum[idx * DDIM + lane + 32], v1);
    }
}

// ---------------------------------------------------------------------------
// Kernel B: EMA update, normalization, new codebook
// ---------------------------------------------------------------------------
__global__ __launch_bounds__(1024) void k_ema(
        const float* __restrict__ ema_cs,
        const float* __restrict__ ema_eis,
        float* __restrict__ out)
{
    __shared__ float red[1024];
    const int k = threadIdx.x;

    float ne = DECAY * ema_cs[k] + ONEMD * g_counts[k];
    out[OFF_ECS + k] = ne;

    red[k] = ne;
    __syncthreads();
    for (int s = 512; s > 0; s >>= 1) {
        if (k < s) red[k] += red[k + s];
        __syncthreads();
    }
    const float n = red[0];

    const float norm = (ne + EPS) / (n + (float)KCB * EPS);
    const float cs   = norm * n;
    const float inv_cs = 1.0f / cs;

    #pragma unroll
    for (int d = 0; d < DDIM; ++d) {
        float eis = DECAY * ema_eis[d * KCB + k] + ONEMD * g_isum[k * DDIM + d];
        out[OFF_EIS + d * KCB + k] = eis;
        float nc = eis * inv_cs;
        out[OFF_NCB + d * KCB + k] = nc;
        g_ncbT[k * DDIM + d] = nc;
    }
}

// ---------------------------------------------------------------------------
// Kernel C: gather + straight-through + loss
// ---------------------------------------------------------------------------
__global__ __launch_bounds__(256) void k_gather_loss(
        const float* __restrict__ X, float* __restrict__ out)
{
    float acc = 0.0f;
    const int total = N_ROWS * DDIM;
    for (int e = blockIdx.x * blockDim.x + threadIdx.x; e < total;
         e += gridDim.x * blockDim.x) {
        int n = e >> 6;
        int d = e & 63;
        float q  = g_ncbT[(g_idx[n] << 6) | d];
        float xv = X[e];
        float df = q - xv;
        out[OFF_Q + e] = xv + df;
        acc = fmaf(df, df, acc);
    }
    #pragma unroll
    for (int o = 16; o > 0; o >>= 1)
        acc += __shfl_down_sync(0xffffffffu, acc, o);
    __shared__ float warpsum[8];
    int lane = threadIdx.x & 31, wid = threadIdx.x >> 5;
    if (lane == 0) warpsum[wid] = acc;
    __syncthreads();
    if (wid == 0) {
        float v = (lane < 8) ? warpsum[lane] : 0.0f;
        #pragma unroll
        for (int o = 4; o > 0; o >>= 1)
            v += __shfl_down_sync(0xffffffffu, v, o);
        if (lane == 0) atomicAdd(g_loss, v);
    }
}

__global__ void k_loss_finalize(float* __restrict__ out) {
    out[OFF_LOSS] = g_loss[0] * (1.0f / (float)(N_ROWS * DDIM));
}

// ---------------------------------------------------------------------------
extern "C" void kernel_launch(void* const* d_in, const int* in_sizes, int n_in,
                              void* d_out, int out_size) {
    const float* X       = (const float*)d_in[0];
    const float* CB      = (const float*)d_in[1];
    const float* EMA_CS  = (const float*)d_in[2];
    const float* EMA_EIS = (const float*)d_in[3];
    float* out = (float*)d_out;

    static const size_t dyn_smem = (KCB + 2 * TILE_FLOATS) * sizeof(float); // 69632
    cudaFuncSetAttribute(k_argmin_scatter,
                         cudaFuncAttributeMaxDynamicSharedMemorySize,
                         (int)dyn_smem);

    k_init<<<256, 256>>>(CB);
    k_argmin_scatter<<<1024, 256, dyn_smem>>>(X);
    k_ema<<<1, 1024>>>(EMA_CS, EMA_EIS, out);
    k_gather_loss<<<2048, 256>>>(X, out);
    k_loss_finalize<<<1, 1>>>(out);
}